// round 16
// baseline (speedup 1.0000x reference)
#include <cuda_runtime.h>
#include <cuda_bf16.h>
#include <cstdint>

#define B_ 256
#define H_ 1024
#define D_ 256
#define C_ 16
#define G_ 32
#define O_ 256
#define HD_ 1280  // H + D

// ---------------- device-global scratch (no cudaMalloc allowed) ----------------
__device__ float g_ebias[C_ * G_ * H_];      // [c][g][h]  = exp2(2.885 * (enc_part + bias))
__device__ float g_pooled[B_ * D_];          // [b][d]
__device__ float g_vsum[C_];                 // [c] = sum_h v[c][h]
__device__ float g_spart[16 * B_ * C_ * G_]; // [nt][b][c][g]  per-h-slice score partials (8MB)

// bf16 hi/lo split operands, plain row-major (k contiguous).
__device__ uint4 g_ah[B_ * H_ / 8];            // A hi  [m][k]   0.5 MB
__device__ uint4 g_al[B_ * H_ / 8];            // A lo
__device__ uint4 g_wh[C_ * H_ * H_ / 8];       // W hi  [c][n][k]  32 MB
__device__ uint4 g_wl[C_ * H_ * H_ / 8];       // W lo

// ---------------- helpers ----------------
__device__ __forceinline__ uint32_t smem_u32(const void* p) {
    uint32_t a;
    asm("{ .reg .u64 t; cvta.to.shared.u64 t, %1; cvt.u32.u64 %0, t; }"
        : "=r"(a) : "l"(p));
    return a;
}
__device__ __forceinline__ void cp16(uint32_t dst, const void* src) {
    asm volatile("cp.async.cg.shared.global [%0], [%1], 16;"
                 :: "r"(dst), "l"(src) : "memory");
}
__device__ __forceinline__ void ldsm4(uint32_t* r, uint32_t addr) {
    asm volatile("ldmatrix.sync.aligned.m8n8.x4.shared.b16 {%0,%1,%2,%3}, [%4];"
                 : "=r"(r[0]), "=r"(r[1]), "=r"(r[2]), "=r"(r[3]) : "r"(addr));
}
__device__ __forceinline__ void mma16816(float* d, const uint32_t* a, const uint32_t* b) {
    asm volatile(
        "mma.sync.aligned.m16n8k16.row.col.f32.bf16.bf16.f32 "
        "{%0,%1,%2,%3}, {%4,%5,%6,%7}, {%8,%9}, {%0,%1,%2,%3};"
        : "+f"(d[0]), "+f"(d[1]), "+f"(d[2]), "+f"(d[3])
        : "r"(a[0]), "r"(a[1]), "r"(a[2]), "r"(a[3]), "r"(b[0]), "r"(b[1]));
}
__device__ __forceinline__ float ex2f(float x) {
    float r;
    asm("ex2.approx.f32 %0, %1;" : "=f"(r) : "f"(x));
    return r;
}
__device__ __forceinline__ float rcpf(float x) {
    float r;
    asm("rcp.approx.f32 %0, %1;" : "=f"(r) : "f"(x));
    return r;
}
#define TANH_SCALE 2.8853900817779268f   // 2 * log2(e)

__device__ __forceinline__ void split8(const float* xs, uint32_t* hw, uint32_t* lw) {
    #pragma unroll
    for (int i = 0; i < 4; i++) {
        __nv_bfloat16 h0 = __float2bfloat16(xs[2*i]);
        __nv_bfloat16 h1 = __float2bfloat16(xs[2*i+1]);
        __nv_bfloat16 l0 = __float2bfloat16(xs[2*i]   - __bfloat162float(h0));
        __nv_bfloat16 l1 = __float2bfloat16(xs[2*i+1] - __bfloat162float(h1));
        hw[i] = (uint32_t)__bfloat16_as_ushort(h0) | ((uint32_t)__bfloat16_as_ushort(h1) << 16);
        lw[i] = (uint32_t)__bfloat16_as_ushort(l0) | ((uint32_t)__bfloat16_as_ushort(l1) << 16);
    }
}

// ---------------- K1 fused: conv_a (blocks 0-127) | ebias (blocks 128-255) ----------------
__global__ void __launch_bounds__(256) pre_kernel(
    const float* __restrict__ hidden, const float* __restrict__ gst_emb,
    const float* __restrict__ attn_w, const float* __restrict__ attn_b)
{
    __shared__ float gs[G_][D_];
    int bx = blockIdx.x;
    int t = threadIdx.x;

    if (bx < 128) {
        int idx = bx * 256 + t;
        int b = idx >> 7, j = idx & 127;
        const float4* s = (const float4*)(hidden + (size_t)b * H_ + j * 8);
        float4 x0 = s[0], x1 = s[1];
        float xs[8] = {x0.x, x0.y, x0.z, x0.w, x1.x, x1.y, x1.z, x1.w};
        uint32_t hw[4], lw[4];
        split8(xs, hw, lw);
        g_ah[b * 128 + j] = make_uint4(hw[0], hw[1], hw[2], hw[3]);
        g_al[b * 128 + j] = make_uint4(lw[0], lw[1], lw[2], lw[3]);
    } else {
        int idx2 = bx - 128;
        int c = idx2 & 15, ob = idx2 >> 4;
        int o = ob * 128 + (t & 127);
        int gbase = (t >> 7) * 16;
        const float4* src = (const float4*)(gst_emb + (size_t)c * G_ * D_);
        for (int i = t; i < G_ * D_ / 4; i += 256)
            ((float4*)gs)[i] = src[i];
        __syncthreads();

        float acc[16];
        #pragma unroll
        for (int g = 0; g < 16; g++) acc[g] = 0.f;

        const float* wrow = attn_w + (size_t)c * H_ * HD_ + (size_t)o * HD_ + H_;
        for (int d = 0; d < D_; d += 4) {
            float4 w4 = *(const float4*)(wrow + d);
            #pragma unroll
            for (int g = 0; g < 16; g++) {
                float a = acc[g];
                a = fmaf(gs[gbase + g][d],     w4.x, a);
                a = fmaf(gs[gbase + g][d + 1], w4.y, a);
                a = fmaf(gs[gbase + g][d + 2], w4.z, a);
                a = fmaf(gs[gbase + g][d + 3], w4.w, a);
                acc[g] = a;
            }
        }
        float bias = attn_b[c * H_ + o];
        #pragma unroll
        for (int g = 0; g < 16; g++)
            g_ebias[(size_t)c * G_ * H_ + (size_t)(gbase + g) * H_ + o] =
                ex2f((acc[g] + bias) * TANH_SCALE);
    }
}

// ---------------- K2: vsum ----------------
__global__ void __launch_bounds__(256) vsum_kernel(const float* __restrict__ v)
{
    int c = blockIdx.x;
    int t = threadIdx.x;
    float s = 0.f;
    #pragma unroll
    for (int p = 0; p < 4; p++) s += v[(size_t)c * H_ + t + p * 256];
    #pragma unroll
    for (int off = 16; off > 0; off >>= 1)
        s += __shfl_xor_sync(0xffffffffu, s, off);
    __shared__ float ws[8];
    if ((t & 31) == 0) ws[t >> 5] = s;
    __syncthreads();
    if (t == 0) {
        float tot = 0.f;
        #pragma unroll
        for (int i = 0; i < 8; i++) tot += ws[i];
        g_vsum[c] = tot;
    }
}

// ---------------- K3: split w_hid -> bf16 hi/lo ----------------
__global__ void __launch_bounds__(256) convert_w_kernel(const float* __restrict__ attn_w)
{
    int idx = blockIdx.x * 256 + threadIdx.x;   // 2,097,152
    int j = idx & 127;
    int o = (idx >> 7) & 1023;
    int c = idx >> 17;
    const float4* s = (const float4*)(attn_w + ((size_t)c * H_ + o) * HD_ + j * 8);
    float4 x0 = s[0], x1 = s[1];
    float xs[8] = {x0.x, x0.y, x0.z, x0.w, x1.x, x1.y, x1.z, x1.w};
    uint32_t hw[4], lw[4];
    split8(xs, hw, lw);
    size_t u = (size_t)c * 131072 + (size_t)o * 128 + j;
    g_wh[u] = make_uint4(hw[0], hw[1], hw[2], hw[3]);
    g_wl[u] = make_uint4(lw[0], lw[1], lw[2], lw[3]);
}

// ---------------- K4: GEMM (BM=128, BN=64) + fused scores epilogue ----------------
// grid (16, 2, 16) = 512 CTAs -> 1.7 waves at 2 CTA/SM: wave-2 mainloops overlap
// wave-1 epilogues.  8 warps: wm = w&3 (32 rows), wn = w>>2 (32 cols).
#define LDROW 80
#define ATILE (128 * LDROW)              // 10240
#define BTILE (64 * LDROW)               // 5120
#define STAGEB (2 * ATILE + 2 * BTILE)   // 30720: Ah, Al, Bh, Bl
#define GSMEM (2 * STAGEB)               // 61440
#define NKC 32
// epilogue scratch (reuses stage smem): Eh[128][68], Ee[32][65], w2[64]
#define EH_OFF 0
#define EE_OFF 34816
#define W2_OFF 43136

__global__ void __launch_bounds__(256, 2) gemm_mma_kernel(const float* __restrict__ v)
{
    extern __shared__ char smem[];
    uint32_t sb = smem_u32(smem);
    int t = threadIdx.x, w = t >> 5, l = t & 31;
    int wm = w & 3, wn = w >> 2;
    int bn0 = blockIdx.x * 64, bm0 = blockIdx.y * 128, c = blockIdx.z;

    const uint4* pAh = g_ah + (size_t)bm0 * 128;
    const uint4* pAl = g_al + (size_t)bm0 * 128;
    const uint4* pBh = g_wh + (size_t)c * 131072 + (size_t)bn0 * 128;
    const uint4* pBl = g_wl + (size_t)c * 131072 + (size_t)bn0 * 128;

    int row = t >> 2, q = t & 3;          // 64 row-groups x 4 chunks

    float acc[2][4][4];
    #pragma unroll
    for (int i = 0; i < 2; i++)
        #pragma unroll
        for (int j = 0; j < 4; j++)
            #pragma unroll
            for (int k = 0; k < 4; k++) acc[i][j][k] = 0.f;

    auto stage_load = [&](int kc, int buf) {
        uint32_t base = sb + buf * STAGEB;
        // A: rows row, row+64 (hi & lo)
        #pragma unroll
        for (int h = 0; h < 2; h++) {
            int r = row + h * 64;
            int su = r * 128 + kc * 4 + q;
            uint32_t d = base + (uint32_t)(r * LDROW + q * 16);
            cp16(d,         pAh + su);
            cp16(d + ATILE, pAl + su);
        }
        // B: row (0..63), hi & lo
        {
            int su = row * 128 + kc * 4 + q;
            uint32_t d = base + 2 * ATILE + (uint32_t)(row * LDROW + q * 16);
            cp16(d,         pBh + su);
            cp16(d + BTILE, pBl + su);
        }
        asm volatile("cp.async.commit_group;" ::: "memory");
    };

    stage_load(0, 0);

    uint32_t arow_off = (uint32_t)((l & 15) * LDROW + (l >> 4) * 16);
    uint32_t brow_off = (uint32_t)((((l & 7) + ((l >> 4) << 3)) * LDROW) + ((l >> 3) & 1) * 16);

    for (int kc = 0; kc < NKC; kc++) {
        int cur = kc & 1;
        if (kc + 1 < NKC) {
            stage_load(kc + 1, cur ^ 1);
            asm volatile("cp.async.wait_group 1;" ::: "memory");
        } else {
            asm volatile("cp.async.wait_group 0;" ::: "memory");
        }
        __syncthreads();

        uint32_t base = sb + cur * STAGEB;
        #pragma unroll
        for (int kk = 0; kk < 2; kk++) {
            uint32_t kkb = kk * 32;
            uint32_t aH[2][4], aL[2][4], bH[2][4], bL[2][4];
            #pragma unroll
            for (int mt = 0; mt < 2; mt++) {
                uint32_t ad = base + (uint32_t)((wm * 32 + mt * 16) * LDROW) + kkb + arow_off;
                ldsm4(aH[mt], ad);
                ldsm4(aL[mt], ad + ATILE);
            }
            #pragma unroll
            for (int p = 0; p < 2; p++) {
                uint32_t bd = base + 2 * ATILE +
                              (uint32_t)((wn * 32 + p * 16) * LDROW) + kkb + brow_off;
                ldsm4(bH[p], bd);
                ldsm4(bL[p], bd + BTILE);
            }
            #pragma unroll
            for (int mt = 0; mt < 2; mt++)
                #pragma unroll
                for (int p = 0; p < 2; p++)
                    #pragma unroll
                    for (int hf = 0; hf < 2; hf++) {
                        int nt = p * 2 + hf;
                        mma16816(acc[mt][nt], aH[mt], &bH[p][hf * 2]);
                        mma16816(acc[mt][nt], aH[mt], &bL[p][hf * 2]);
                        mma16816(acc[mt][nt], aL[mt], &bH[p][hf * 2]);
                    }
        }
        __syncthreads();
    }

    // ---- fused scores epilogue (reuses stage smem) ----
    float* Eh_s = (float*)(smem + EH_OFF);    // [128][68]
    float* Ee_s = (float*)(smem + EE_OFF);    // [32][65]
    float* w2_s = (float*)(smem + W2_OFF);    // [64]

    #pragma unroll
    for (int mt = 0; mt < 2; mt++) {
        int m0 = wm * 32 + mt * 16 + (l >> 2);
        #pragma unroll
        for (int nt = 0; nt < 4; nt++) {
            int col = wn * 32 + nt * 8 + (l & 3) * 2;
            Eh_s[m0 * 68 + col]           = ex2f(acc[mt][nt][0] * TANH_SCALE);
            Eh_s[m0 * 68 + col + 1]       = ex2f(acc[mt][nt][1] * TANH_SCALE);
            Eh_s[(m0 + 8) * 68 + col]     = ex2f(acc[mt][nt][2] * TANH_SCALE);
            Eh_s[(m0 + 8) * 68 + col + 1] = ex2f(acc[mt][nt][3] * TANH_SCALE);
        }
    }
    #pragma unroll
    for (int p = 0; p < 8; p++) {
        int i = t + p * 256;                 // 0..2047 over 32g x 64col
        int g = i >> 6, col = i & 63;
        Ee_s[g * 65 + col] = g_ebias[(size_t)c * (G_ * H_) + (size_t)g * H_ + bn0 + col];
    }
    if (t < 64)
        w2_s[t] = -2.0f * v[(size_t)c * H_ + bn0 + t];
    __syncthreads();

    {
        int g = l;
        float s[16];
        #pragma unroll
        for (int r = 0; r < 16; r++) s[r] = 0.f;
        #pragma unroll 2
        for (int col = 0; col < 64; col++) {
            float ee  = Ee_s[g * 65 + col];
            float w2v = w2_s[col];
            #pragma unroll
            for (int r = 0; r < 16; r++) {
                float eh = Eh_s[(w + r * 8) * 68 + col];   // broadcast
                s[r] = fmaf(w2v, rcpf(fmaf(eh, ee, 1.f)), s[r]);
            }
        }
        int ntid = blockIdx.x;   // 0..15
        #pragma unroll
        for (int r = 0; r < 16; r++) {
            int b = bm0 + w + r * 8;
            g_spart[(((size_t)ntid * B_ + b) * C_ + c) * G_ + g] = s[r];
        }
    }
}

// ---------------- K5: finalize — sum partials + softmax -> att ----------------
__global__ void __launch_bounds__(512) finalize_kernel(float* __restrict__ att)
{
    int b = blockIdx.x;
    int c = threadIdx.x >> 5;
    int g = threadIdx.x & 31;
    float s = g_vsum[c];
    #pragma unroll
    for (int nt = 0; nt < 16; nt++)
        s += g_spart[(((size_t)nt * B_ + b) * C_ + c) * G_ + g];
    float m = s;
    #pragma unroll
    for (int off = 16; off > 0; off >>= 1)
        m = fmaxf(m, __shfl_xor_sync(0xffffffffu, m, off));
    float e = __expf(s - m);
    float sum = e;
    #pragma unroll
    for (int off = 16; off > 0; off >>= 1)
        sum += __shfl_xor_sync(0xffffffffu, sum, off);
    att[(size_t)b * (C_ * G_) + c * G_ + g] = e / sum;
}

// ---------------- K6: pooled ----------------
__global__ void __launch_bounds__(256) pooled_kernel(
    const float* __restrict__ att, const float* __restrict__ gst_emb)
{
    int b0 = blockIdx.x * 4;
    int d = threadIdx.x;
    __shared__ float attS[4][C_ * G_];
    #pragma unroll
    for (int p = 0; p < 8; p++) {
        int idx = threadIdx.x + p * 256;
        attS[idx >> 9][idx & 511] = att[(size_t)b0 * 512 + idx];
    }
    __syncthreads();
    float acc[4];
    #pragma unroll
    for (int i = 0; i < 4; i++) acc[i] = 0.f;
    #pragma unroll 4
    for (int cg = 0; cg < C_ * G_; cg++) {
        float e = gst_emb[(size_t)cg * D_ + d];
        #pragma unroll
        for (int i = 0; i < 4; i++) acc[i] = fmaf(attS[i][cg], e, acc[i]);
    }
    #pragma unroll
    for (int i = 0; i < 4; i++)
        g_pooled[(size_t)(b0 + i) * D_ + d] = acc[i] * (1.0f / C_);
}

// ---------------- K7: out ----------------
__global__ void __launch_bounds__(256) out_kernel(
    const float* __restrict__ out_w, const float* __restrict__ out_b,
    float* __restrict__ outp)
{
    int b0 = blockIdx.x * 8;
    int o = threadIdx.x;
    __shared__ float ps[8][D_];
    #pragma unroll
    for (int p = 0; p < 8; p++) {
        int idx = threadIdx.x + p * 256;
        ps[idx >> 8][idx & 255] = g_pooled[(size_t)b0 * D_ + idx];
    }
    __syncthreads();
    float acc[8];
    #pragma unroll
    for (int i = 0; i < 8; i++) acc[i] = 0.f;
    const float* wrow = out_w + (size_t)o * D_;
    for (int dd = 0; dd < D_; dd += 4) {
        float4 w4 = *(const float4*)(wrow + dd);
        #pragma unroll
        for (int i = 0; i < 8; i++) {
            float a = acc[i];
            a = fmaf(ps[i][dd],     w4.x, a);
            a = fmaf(ps[i][dd + 1], w4.y, a);
            a = fmaf(ps[i][dd + 2], w4.z, a);
            a = fmaf(ps[i][dd + 3], w4.w, a);
            acc[i] = a;
        }
    }
    float bias = out_b[o];
    #pragma unroll
    for (int i = 0; i < 8; i++)
        outp[(size_t)(b0 + i) * O_ + o] = acc[i] + bias;
}

extern "C" void kernel_launch(void* const* d_in, const int* in_sizes, int n_in,
                              void* d_out, int out_size)
{
    const float* hidden  = (const float*)d_in[0];
    const float* gst_emb = (const float*)d_in[1];
    const float* attn_w  = (const float*)d_in[2];
    const float* attn_b  = (const float*)d_in[3];
    const float* v       = (const float*)d_in[4];
    const float* out_w   = (const float*)d_in[5];
    const float* out_b   = (const float*)d_in[6];
    float* out  = (float*)d_out;
    float* att  = out;                   // [B, C*G]
    float* outp = out + B_ * C_ * G_;    // [B, O]

    cudaFuncSetAttribute(gemm_mma_kernel,
                         cudaFuncAttributeMaxDynamicSharedMemorySize, GSMEM);

    // Launch order: gemm (with fused scores) sits in the ncu capture slot (4th launch).
    pre_kernel      <<<256,  256>>>(hidden, gst_emb, attn_w, attn_b);
    vsum_kernel     <<<C_,   256>>>(v);
    convert_w_kernel<<<8192, 256>>>(attn_w);
    gemm_mma_kernel <<<dim3(16, 2, C_), 256, GSMEM>>>(v);
    finalize_kernel <<<B_,   512>>>(att);
    pooled_kernel   <<<B_ / 4, 256>>>(att, gst_emb);
    out_kernel      <<<B_ / 8, 256>>>(out_w, out_b, outp);
}

// round 17
// speedup vs baseline: 1.1838x; 1.1838x over previous
#include <cuda_runtime.h>
#include <cuda_bf16.h>
#include <cstdint>

#define B_ 256
#define H_ 1024
#define D_ 256
#define C_ 16
#define G_ 32
#define O_ 256
#define HD_ 1280  // H + D

// ---------------- device-global scratch (no cudaMalloc allowed) ----------------
__device__ float g_ebias[C_ * G_ * H_];     // [c][g][h] = exp2(2.885*(enc_part+bias))
__device__ float g_vsum[C_];                // [c] = sum_h v[c][h]
__device__ float g_spart[8 * B_ * C_ * G_]; // [nt][b][c][g] per-h-slice score partials

// bf16 hi/lo split operands, plain row-major (k contiguous).
__device__ uint4 g_ah[B_ * H_ / 8];            // A hi  [m][k]
__device__ uint4 g_al[B_ * H_ / 8];            // A lo
__device__ uint4 g_wh[C_ * H_ * H_ / 8];       // W hi  [c][n][k]
__device__ uint4 g_wl[C_ * H_ * H_ / 8];       // W lo

// ---------------- helpers ----------------
__device__ __forceinline__ uint32_t smem_u32(const void* p) {
    uint32_t a;
    asm("{ .reg .u64 t; cvta.to.shared.u64 t, %1; cvt.u32.u64 %0, t; }"
        : "=r"(a) : "l"(p));
    return a;
}
__device__ __forceinline__ void cp16(uint32_t dst, const void* src) {
    asm volatile("cp.async.cg.shared.global [%0], [%1], 16;"
                 :: "r"(dst), "l"(src) : "memory");
}
__device__ __forceinline__ void ldsm4(uint32_t* r, uint32_t addr) {
    asm volatile("ldmatrix.sync.aligned.m8n8.x4.shared.b16 {%0,%1,%2,%3}, [%4];"
                 : "=r"(r[0]), "=r"(r[1]), "=r"(r[2]), "=r"(r[3]) : "r"(addr));
}
__device__ __forceinline__ void mma16816(float* d, const uint32_t* a, const uint32_t* b) {
    asm volatile(
        "mma.sync.aligned.m16n8k16.row.col.f32.bf16.bf16.f32 "
        "{%0,%1,%2,%3}, {%4,%5,%6,%7}, {%8,%9}, {%0,%1,%2,%3};"
        : "+f"(d[0]), "+f"(d[1]), "+f"(d[2]), "+f"(d[3])
        : "r"(a[0]), "r"(a[1]), "r"(a[2]), "r"(a[3]), "r"(b[0]), "r"(b[1]));
}
__device__ __forceinline__ float ex2f(float x) {
    float r;
    asm("ex2.approx.f32 %0, %1;" : "=f"(r) : "f"(x));
    return r;
}
__device__ __forceinline__ float rcpf(float x) {
    float r;
    asm("rcp.approx.f32 %0, %1;" : "=f"(r) : "f"(x));
    return r;
}
#define TANH_SCALE 2.8853900817779268f   // 2 * log2(e)

__device__ __forceinline__ void split8(const float* xs, uint32_t* hw, uint32_t* lw) {
    #pragma unroll
    for (int i = 0; i < 4; i++) {
        __nv_bfloat16 h0 = __float2bfloat16(xs[2*i]);
        __nv_bfloat16 h1 = __float2bfloat16(xs[2*i+1]);
        __nv_bfloat16 l0 = __float2bfloat16(xs[2*i]   - __bfloat162float(h0));
        __nv_bfloat16 l1 = __float2bfloat16(xs[2*i+1] - __bfloat162float(h1));
        hw[i] = (uint32_t)__bfloat16_as_ushort(h0) | ((uint32_t)__bfloat16_as_ushort(h1) << 16);
        lw[i] = (uint32_t)__bfloat16_as_ushort(l0) | ((uint32_t)__bfloat16_as_ushort(l1) << 16);
    }
}

// ---------------- K1: everything before the GEMM, one launch ----------------
// blocks 0-127: conv_a | 128-255: ebias | 256-271: vsum | 272-8463: conv_w
__global__ void __launch_bounds__(256) pre_all_kernel(
    const float* __restrict__ hidden, const float* __restrict__ gst_emb,
    const float* __restrict__ attn_w, const float* __restrict__ attn_b,
    const float* __restrict__ v)
{
    __shared__ float gs[G_][D_];
    int bx = blockIdx.x;
    int t = threadIdx.x;

    if (bx >= 272) {
        // ---- conv_w: split w_hid -> bf16 hi/lo ----
        int idx = (bx - 272) * 256 + t;     // 0..2,097,151
        int j = idx & 127;
        int o = (idx >> 7) & 1023;
        int c = idx >> 17;
        const float4* s = (const float4*)(attn_w + ((size_t)c * H_ + o) * HD_ + j * 8);
        float4 x0 = s[0], x1 = s[1];
        float xs[8] = {x0.x, x0.y, x0.z, x0.w, x1.x, x1.y, x1.z, x1.w};
        uint32_t hw[4], lw[4];
        split8(xs, hw, lw);
        size_t u = (size_t)c * 131072 + (size_t)o * 128 + j;
        g_wh[u] = make_uint4(hw[0], hw[1], hw[2], hw[3]);
        g_wl[u] = make_uint4(lw[0], lw[1], lw[2], lw[3]);
    } else if (bx < 128) {
        // ---- conv_a ----
        int idx = bx * 256 + t;
        int b = idx >> 7, j = idx & 127;
        const float4* s = (const float4*)(hidden + (size_t)b * H_ + j * 8);
        float4 x0 = s[0], x1 = s[1];
        float xs[8] = {x0.x, x0.y, x0.z, x0.w, x1.x, x1.y, x1.z, x1.w};
        uint32_t hw[4], lw[4];
        split8(xs, hw, lw);
        g_ah[b * 128 + j] = make_uint4(hw[0], hw[1], hw[2], hw[3]);
        g_al[b * 128 + j] = make_uint4(lw[0], lw[1], lw[2], lw[3]);
    } else if (bx < 256) {
        // ---- ebias -> exp2 domain ----
        int idx2 = bx - 128;
        int c = idx2 & 15, ob = idx2 >> 4;
        int o = ob * 128 + (t & 127);
        int gbase = (t >> 7) * 16;
        const float4* src = (const float4*)(gst_emb + (size_t)c * G_ * D_);
        for (int i = t; i < G_ * D_ / 4; i += 256)
            ((float4*)gs)[i] = src[i];
        __syncthreads();

        float acc[16];
        #pragma unroll
        for (int g = 0; g < 16; g++) acc[g] = 0.f;

        const float* wrow = attn_w + (size_t)c * H_ * HD_ + (size_t)o * HD_ + H_;
        for (int d = 0; d < D_; d += 4) {
            float4 w4 = *(const float4*)(wrow + d);
            #pragma unroll
            for (int g = 0; g < 16; g++) {
                float a = acc[g];
                a = fmaf(gs[gbase + g][d],     w4.x, a);
                a = fmaf(gs[gbase + g][d + 1], w4.y, a);
                a = fmaf(gs[gbase + g][d + 2], w4.z, a);
                a = fmaf(gs[gbase + g][d + 3], w4.w, a);
                acc[g] = a;
            }
        }
        float bias = attn_b[c * H_ + o];
        #pragma unroll
        for (int g = 0; g < 16; g++)
            g_ebias[(size_t)c * G_ * H_ + (size_t)(gbase + g) * H_ + o] =
                ex2f((acc[g] + bias) * TANH_SCALE);
    } else {
        // ---- vsum ----
        int c = bx - 256;
        float s = 0.f;
        #pragma unroll
        for (int p = 0; p < 4; p++) s += v[(size_t)c * H_ + t + p * 256];
        #pragma unroll
        for (int off = 16; off > 0; off >>= 1)
            s += __shfl_xor_sync(0xffffffffu, s, off);
        __shared__ float ws[8];
        if ((t & 31) == 0) ws[t >> 5] = s;
        __syncthreads();
        if (t == 0) {
            float tot = 0.f;
            #pragma unroll
            for (int i = 0; i < 8; i++) tot += ws[i];
            g_vsum[c] = tot;
        }
    }
}

// ---------------- K2: GEMM (R13 geometry) + batch-inverted scores epilogue ----------------
#define LDROW 80
#define TILEB (128 * LDROW)
#define STAGEB (4 * TILEB)
#define GSMEM 85120            // epilogue: Eh[128][132] + Ee[32][133] + w2[128]
#define NKC 32

__global__ void __launch_bounds__(256, 2) gemm_mma_kernel(const float* __restrict__ v)
{
    extern __shared__ char smem[];
    uint32_t sb = smem_u32(smem);
    int t = threadIdx.x, w = t >> 5, l = t & 31;
    int wm = w & 1, wn = w >> 1;
    int bn0 = blockIdx.x * 128, bm0 = blockIdx.y * 128, c = blockIdx.z;

    const uint4* pAh = g_ah + (size_t)bm0 * 128;
    const uint4* pAl = g_al + (size_t)bm0 * 128;
    const uint4* pBh = g_wh + (size_t)c * 131072 + (size_t)bn0 * 128;
    const uint4* pBl = g_wl + (size_t)c * 131072 + (size_t)bn0 * 128;

    int row = t >> 2, q = t & 3;
    uint32_t cpdst = (uint32_t)(row * LDROW + q * 16);

    float acc[4][4][4];
    #pragma unroll
    for (int i = 0; i < 4; i++)
        #pragma unroll
        for (int j = 0; j < 4; j++)
            #pragma unroll
            for (int k = 0; k < 4; k++) acc[i][j][k] = 0.f;

    auto stage_load = [&](int kc, int buf) {
        uint32_t base = sb + buf * STAGEB;
        #pragma unroll
        for (int h = 0; h < 2; h++) {
            int r = row + h * 64;
            int su = r * 128 + kc * 4 + q;
            uint32_t d = base + cpdst + h * 64 * LDROW;
            cp16(d,              pAh + su);
            cp16(d + TILEB,      pAl + su);
            cp16(d + 2 * TILEB,  pBh + su);
            cp16(d + 3 * TILEB,  pBl + su);
        }
        asm volatile("cp.async.commit_group;" ::: "memory");
    };

    stage_load(0, 0);

    uint32_t arow_off = (uint32_t)((l & 15) * LDROW + (l >> 4) * 16);
    uint32_t brow_off = (uint32_t)((((l & 7) + ((l >> 4) << 3)) * LDROW) + ((l >> 3) & 1) * 16);

    for (int kc = 0; kc < NKC; kc++) {
        int cur = kc & 1;
        if (kc + 1 < NKC) {
            stage_load(kc + 1, cur ^ 1);
            asm volatile("cp.async.wait_group 1;" ::: "memory");
        } else {
            asm volatile("cp.async.wait_group 0;" ::: "memory");
        }
        __syncthreads();

        uint32_t base = sb + cur * STAGEB;
        #pragma unroll
        for (int kk = 0; kk < 2; kk++) {
            uint32_t kkb = kk * 32;
            uint32_t aH[4][4], aL[4][4], bH[2][4], bL[2][4];
            #pragma unroll
            for (int mt = 0; mt < 4; mt++) {
                uint32_t ad = base + (uint32_t)((wm * 64 + mt * 16) * LDROW) + kkb + arow_off;
                ldsm4(aH[mt], ad);
                ldsm4(aL[mt], ad + TILEB);
            }
            #pragma unroll
            for (int p = 0; p < 2; p++) {
                uint32_t bd = base + 2 * TILEB +
                              (uint32_t)((wn * 32 + p * 16) * LDROW) + kkb + brow_off;
                ldsm4(bH[p], bd);
                ldsm4(bL[p], bd + TILEB);
            }
            #pragma unroll
            for (int mt = 0; mt < 4; mt++)
                #pragma unroll
                for (int p = 0; p < 2; p++)
                    #pragma unroll
                    for (int hf = 0; hf < 2; hf++) {
                        int nt = p * 2 + hf;
                        mma16816(acc[mt][nt], aH[mt], &bH[p][hf * 2]);
                        mma16816(acc[mt][nt], aH[mt], &bL[p][hf * 2]);
                        mma16816(acc[mt][nt], aL[mt], &bH[p][hf * 2]);
                    }
        }
        __syncthreads();
    }

    // ---- fused scores epilogue (batch-4 Montgomery inversion: 1 MUFU / 4 rcp) ----
    float* Eh_s = (float*)smem;                       // [128][132]
    float* Ee_s = (float*)(smem + 67584);             // [32][133]
    float* w2_s = (float*)(smem + 67584 + 17024);     // [128]

    #pragma unroll
    for (int mt = 0; mt < 4; mt++) {
        int m0 = wm * 64 + mt * 16 + (l >> 2);
        #pragma unroll
        for (int nt = 0; nt < 4; nt++) {
            int col = wn * 32 + nt * 8 + (l & 3) * 2;
            Eh_s[m0 * 132 + col]           = ex2f(acc[mt][nt][0] * TANH_SCALE);
            Eh_s[m0 * 132 + col + 1]       = ex2f(acc[mt][nt][1] * TANH_SCALE);
            Eh_s[(m0 + 8) * 132 + col]     = ex2f(acc[mt][nt][2] * TANH_SCALE);
            Eh_s[(m0 + 8) * 132 + col + 1] = ex2f(acc[mt][nt][3] * TANH_SCALE);
        }
    }
    #pragma unroll
    for (int p = 0; p < 16; p++) {
        int i = t + p * 256;                 // 32g x 128col
        int g = i >> 7, col = i & 127;
        Ee_s[g * 133 + col] = g_ebias[(size_t)c * (G_ * H_) + (size_t)g * H_ + bn0 + col];
    }
    if (t < 128)
        w2_s[t] = -2.0f * v[(size_t)c * H_ + bn0 + t];
    __syncthreads();

    {
        int g = l;
        float s[16];
        #pragma unroll
        for (int r = 0; r < 16; r++) s[r] = 0.f;
        #pragma unroll 2
        for (int col = 0; col < 128; col++) {
            float ee  = Ee_s[g * 133 + col];
            float w2v = w2_s[col];
            #pragma unroll
            for (int rq = 0; rq < 16; rq += 4) {
                float d0 = fmaf(Eh_s[(w + (rq + 0) * 8) * 132 + col], ee, 1.f);
                float d1 = fmaf(Eh_s[(w + (rq + 1) * 8) * 132 + col], ee, 1.f);
                float d2 = fmaf(Eh_s[(w + (rq + 2) * 8) * 132 + col], ee, 1.f);
                float d3 = fmaf(Eh_s[(w + (rq + 3) * 8) * 132 + col], ee, 1.f);
                float p1 = d0 * d1;
                float p2 = p1 * d2;
                float p3 = p2 * d3;
                float inv  = rcpf(p3);        // 1/(d0 d1 d2 d3)
                float r3   = p2 * inv;        // 1/d3
                float inv2 = inv * d3;        // 1/(d0 d1 d2)
                float r2   = p1 * inv2;       // 1/d2
                float inv1 = inv2 * d2;       // 1/(d0 d1)
                float r1   = d0 * inv1;       // 1/d1
                float r0   = d1 * inv1;       // 1/d0
                s[rq + 0] = fmaf(w2v, r0, s[rq + 0]);
                s[rq + 1] = fmaf(w2v, r1, s[rq + 1]);
                s[rq + 2] = fmaf(w2v, r2, s[rq + 2]);
                s[rq + 3] = fmaf(w2v, r3, s[rq + 3]);
            }
        }
        int ntid = blockIdx.x;
        #pragma unroll
        for (int r = 0; r < 16; r++) {
            int b = bm0 + w + r * 8;
            g_spart[(((size_t)ntid * B_ + b) * C_ + c) * G_ + g] = s[r];
        }
    }
}

// ---------------- K3: tail — finalize + pooled + out, one launch ----------------
// 64 blocks x 256 threads; block owns 4 b rows end-to-end (att reused via smem).
__global__ void __launch_bounds__(256) tail_kernel(
    float* __restrict__ att, const float* __restrict__ gst_emb,
    const float* __restrict__ out_w, const float* __restrict__ out_b,
    float* __restrict__ outp)
{
    int b0 = blockIdx.x * 4;
    int t = threadIdx.x;
    __shared__ float attS[4][C_ * G_];
    __shared__ float ps[4][D_];

    // finalize: sum 8 partials + warp softmax (warp = fixed (b,c), lanes = g)
    #pragma unroll
    for (int i = 0; i < 8; i++) {
        int idx = t + i * 256;           // 0..2047 = 4b x 512cg
        int bb = idx >> 9, cg = idx & 511;
        int c = cg >> 5;
        int b = b0 + bb;
        float s = g_vsum[c];
        #pragma unroll
        for (int nt = 0; nt < 8; nt++)
            s += g_spart[(((size_t)nt * B_ + b) * C_ + c) * G_ + (cg & 31)];
        float m = s;
        #pragma unroll
        for (int off = 16; off > 0; off >>= 1)
            m = fmaxf(m, __shfl_xor_sync(0xffffffffu, m, off));
        float e = __expf(s - m);
        float sum = e;
        #pragma unroll
        for (int off = 16; off > 0; off >>= 1)
            sum += __shfl_xor_sync(0xffffffffu, sum, off);
        float a = e / sum;
        attS[bb][cg] = a;
        att[(size_t)b * (C_ * G_) + cg] = a;
    }
    __syncthreads();

    // pooled: d = t
    {
        float acc[4];
        #pragma unroll
        for (int i = 0; i < 4; i++) acc[i] = 0.f;
        #pragma unroll 4
        for (int cg = 0; cg < C_ * G_; cg++) {
            float e = gst_emb[(size_t)cg * D_ + t];
            #pragma unroll
            for (int i = 0; i < 4; i++) acc[i] = fmaf(attS[i][cg], e, acc[i]);
        }
        #pragma unroll
        for (int i = 0; i < 4; i++) ps[i][t] = acc[i] * (1.0f / C_);
    }
    __syncthreads();

    // out: o = t
    {
        float acc[4];
        #pragma unroll
        for (int i = 0; i < 4; i++) acc[i] = 0.f;
        const float* wrow = out_w + (size_t)t * D_;
        for (int dd = 0; dd < D_; dd += 4) {
            float4 w4 = *(const float4*)(wrow + dd);
            #pragma unroll
            for (int i = 0; i < 4; i++) {
                float a = acc[i];
                a = fmaf(ps[i][dd],     w4.x, a);
                a = fmaf(ps[i][dd + 1], w4.y, a);
                a = fmaf(ps[i][dd + 2], w4.z, a);
                a = fmaf(ps[i][dd + 3], w4.w, a);
                acc[i] = a;
            }
        }
        float bias = out_b[t];
        #pragma unroll
        for (int i = 0; i < 4; i++)
            outp[(size_t)(b0 + i) * O_ + t] = acc[i] + bias;
    }
}

extern "C" void kernel_launch(void* const* d_in, const int* in_sizes, int n_in,
                              void* d_out, int out_size)
{
    const float* hidden  = (const float*)d_in[0];
    const float* gst_emb = (const float*)d_in[1];
    const float* attn_w  = (const float*)d_in[2];
    const float* attn_b  = (const float*)d_in[3];
    const float* v       = (const float*)d_in[4];
    const float* out_w   = (const float*)d_in[5];
    const float* out_b   = (const float*)d_in[6];
    float* out  = (float*)d_out;
    float* att  = out;                   // [B, C*G]
    float* outp = out + B_ * C_ * G_;    // [B, O]

    cudaFuncSetAttribute(gemm_mma_kernel,
                         cudaFuncAttributeMaxDynamicSharedMemorySize, GSMEM);

    pre_all_kernel<<<8464, 256>>>(hidden, gst_emb, attn_w, attn_b, v);
    gemm_mma_kernel<<<dim3(8, 2, C_), 256, GSMEM>>>(v);
    tail_kernel   <<<B_ / 4, 256>>>(att, gst_emb, out_w, out_b, outp);
}